// round 15
// baseline (speedup 1.0000x reference)
#include <cuda_runtime.h>
#include <cuda_bf16.h>
#include <math.h>

#define Dq    256
#define Bq    8
#define Tq    32
#define NCOLS 256
#define NX    4224
#define BETAq 0.8f

typedef __nv_bfloat16 bf16;

// ------------ device scratch (no allocations) ------------
__device__ __align__(256) bf16 g_psih_r[Dq*NCOLS];
__device__ __align__(256) bf16 g_psih_i[Dq*NCOLS];
__device__ __align__(256) bf16 g_Wh_r[Dq*Tq*256];   // 256 x 8192, ld 8192
__device__ __align__(256) bf16 g_Wh_i[Dq*Tq*256];
__device__ __align__(256) bf16 g_Ph_r[4*Dq*Dq];     // Uh^2, Uh^4, Uh^8, Uh^16
__device__ __align__(256) bf16 g_Ph_i[4*Dq*Dq];
__device__ __align__(256) bf16 g_Gh_r[Tq*256*Dq];   // 8192 x 256, ld 256 (conj(M)*Uh^ap)
__device__ __align__(256) bf16 g_Gh_i[Tq*256*Dq];
__device__ __align__(256) bf16 g_G2h_r[Tq*256*Dq];  // G' = G * Ux, 8192 x 256
__device__ __align__(256) bf16 g_G2h_i[Tq*256*Dq];
__device__ __align__(256) bf16 g_Uxh_r[Dq*Dq], g_Uxh_i[Dq*Dq];
__device__ __align__(256) bf16 g_Uhh_r[Dq*Dq], g_Uhh_i[Dq*Dq];
__device__ __align__(256) float g_probs[Tq*Bq*256]; // (t*8+b)*256 + k
__device__ float g_gpow[64];
__device__ float g_lb2;
__device__ int   g_map_src[NX];
__device__ int   g_map_a[NX];
__device__ int   g_map_tb[NX];

// measure tile prefix offsets: off[ap+1]-off[ap] = ceil(4*(32-ap)*(33-ap)/64)
__constant__ int c_off[33] = {0,66,128,187,242,293,341,385,426,464,499,531,560,587,
                              611,633,653,670,685,699,711,721,730,737,743,748,752,
                              755,757,759,760,761,762};

// ------------ merged prep: maps | psi | norm+probs | convU ------------
__global__ void prep_all(const float* __restrict__ Lambda,
                         const float* __restrict__ xt, const float* __restrict__ xa,
                         const float* __restrict__ xv, const float* __restrict__ smask,
                         const float* __restrict__ Wt, const float* __restrict__ bt,
                         const float* __restrict__ Wa, const float* __restrict__ ba,
                         const float* __restrict__ Wv, const float* __restrict__ bv,
                         const float* __restrict__ Pt, const float* __restrict__ Pa,
                         const float* __restrict__ Pv,
                         const float* __restrict__ Kr, const float* __restrict__ Ki,
                         const float* __restrict__ Uxr, const float* __restrict__ Uxi,
                         const float* __restrict__ Uhr, const float* __restrict__ Uhi)
{
    int bx = blockIdx.x;
    int tid = threadIdx.x;   // 256

    if (bx < 17) {
        // ---- maps + global scalars ----
        if (bx == 0 && tid == 0) {
            float lam = 1.f / (1.f + expf(-Lambda[0]));
            float g = 1.f - lam;
            float p = 1.f;
            for (int i = 0; i < 64; i++) { g_gpow[i] = p; p *= g; }
            g_lb2 = lam * lam * BETAq * BETAq;
        }
        int col = bx * 256 + tid;
        if (col >= NX) return;
        int q = col >> 3, b = col & 7;
        int s = 0;
        while ((s + 1) * (s + 2) / 2 <= q) s++;
        int a = q - s * (s + 1) / 2;
        g_map_src[col] = a * 256 + (s - a) * 8 + b;
        g_map_a[col] = a;
        g_map_tb[col] = s * 8 + b;
        return;
    }

    if (bx < 273) {
        // ---- psi block ----
        int blk = bx - 17;
        int b = blk >> 5, t = blk & 31;
        __shared__ float tr[4], ti[4], ar[8], ai[8], vr[8], vi[8];
        __shared__ float h[8];
        __shared__ int spk;

        if (tid == 0) {
            float s0 = smask[(b*Tq + t)*2 + 0];
            float s1 = smask[(b*Tq + t)*2 + 1];
            spk = (s0 >= s1) ? 0 : 1;
        }
        __syncthreads();

        if (tid < 4) {
            const float* x = xt + (b*Tq + t)*300;
            float acc = bt[tid];
            for (int i = 0; i < 300; i++) acc = fmaf(x[i], Wt[i*4 + tid], acc);
            h[tid] = fmaxf(acc, 0.f);
        }
        __syncthreads();
        if (tid == 0) {
            float n = 0.f;
            for (int j = 0; j < 4; j++) n += h[j]*h[j];
            n = fmaxf(sqrtf(n), 1e-12f);
            for (int j = 0; j < 4; j++) {
                float a = h[j]/n, p = Pt[spk*4 + j];
                tr[j] = a*cosf(p); ti[j] = a*sinf(p);
            }
        }
        __syncthreads();

        if (tid < 8) {
            const float* x = xa + (b*Tq + t)*74;
            float acc = ba[tid];
            for (int i = 0; i < 74; i++) acc = fmaf(x[i], Wa[i*8 + tid], acc);
            h[tid] = fmaxf(acc, 0.f);
        }
        __syncthreads();
        if (tid == 0) {
            float n = 0.f;
            for (int j = 0; j < 8; j++) n += h[j]*h[j];
            n = fmaxf(sqrtf(n), 1e-12f);
            for (int j = 0; j < 8; j++) {
                float a = h[j]/n, p = Pa[spk*8 + j];
                ar[j] = a*cosf(p); ai[j] = a*sinf(p);
            }
        }
        __syncthreads();

        if (tid < 8) {
            const float* x = xv + (b*Tq + t)*35;
            float acc = bv[tid];
            for (int i = 0; i < 35; i++) acc = fmaf(x[i], Wv[i*8 + tid], acc);
            h[tid] = fmaxf(acc, 0.f);
        }
        __syncthreads();
        if (tid == 0) {
            float n = 0.f;
            for (int j = 0; j < 8; j++) n += h[j]*h[j];
            n = fmaxf(sqrtf(n), 1e-12f);
            for (int j = 0; j < 8; j++) {
                float a = h[j]/n, p = Pv[spk*8 + j];
                vr[j] = a*cosf(p); vi[j] = a*sinf(p);
            }
        }
        __syncthreads();

        int col = t*8 + b;
        int idx = tid;   // 256 threads cover 256 elements
        int it = idx >> 6, ia = (idx >> 3) & 7, iv = idx & 7;
        float pr = tr[it]*ar[ia] - ti[it]*ai[ia];
        float pi = tr[it]*ai[ia] + ti[it]*ar[ia];
        g_psih_r[idx*NCOLS + col] = __float2bfloat16(pr*vr[iv] - pi*vi[iv]);
        g_psih_i[idx*NCOLS + col] = __float2bfloat16(pr*vi[iv] + pi*vr[iv]);
        return;
    }

    if (bx < 529) {
        // ---- norm_m row + probs init ----
        int k = bx - 273;
        __shared__ float red[256];
        float a = Kr[k*256 + tid], c = Ki[k*256 + tid];
        red[tid] = a*a + c*c;
        __syncthreads();
        for (int st = 128; st > 0; st >>= 1) {
            if (tid < st) red[tid] += red[tid + st];
            __syncthreads();
        }
        float inv = 1.f / sqrtf(red[0]);
        g_Gh_r[k*256 + tid] = __float2bfloat16( Kr[k*256 + tid] * inv);
        g_Gh_i[k*256 + tid] = __float2bfloat16(-Ki[k*256 + tid] * inv);
        // probs init: row k of probs corresponds to tb=k, t = k>>3; compute S locally
        float lam = 1.f / (1.f + expf(-Lambda[0]));
        float g = 1.f - lam;
        int t = k >> 3;
        float gt1 = 1.f;
        for (int i = 0; i <= t; i++) gt1 *= g;
        float S = BETAq * (lam * BETAq * (float)(t + 1) * gt1
                           + (1.f - BETAq) * (1.f - gt1) + gt1) + (1.f - BETAq);
        g_probs[k*256 + tid] = S / 256.f;
        return;
    }

    // ---- convU ----
    int i = (bx - 529) * 256 + tid;
    g_Uxh_r[i] = __float2bfloat16(Uxr[i]);
    g_Uxh_i[i] = __float2bfloat16(Uxi[i]);
    g_Uhh_r[i] = __float2bfloat16(Uhr[i]);
    g_Uhh_i[i] = __float2bfloat16(Uhi[i]);
}

// ------------ bf16 mma + cp.async + ldmatrix helpers ------------
#define MMA16(C, A, B)                                                             \
    asm volatile("mma.sync.aligned.m16n8k16.row.col.f32.bf16.bf16.f32 "           \
                 "{%0,%1,%2,%3},{%4,%5,%6,%7},{%8,%9},{%0,%1,%2,%3};"              \
                 : "+f"((C)[0]), "+f"((C)[1]), "+f"((C)[2]), "+f"((C)[3])          \
                 : "r"((A)[0]), "r"((A)[1]), "r"((A)[2]), "r"((A)[3]),             \
                   "r"((B)[0]), "r"((B)[1]))

#define LDSM4(R, addr) \
    asm volatile("ldmatrix.sync.aligned.m8n8.x4.shared.b16 {%0,%1,%2,%3}, [%4];" \
                 : "=r"((R)[0]), "=r"((R)[1]), "=r"((R)[2]), "=r"((R)[3]) : "r"(addr))

#define LDSMT4(R, addr) \
    asm volatile("ldmatrix.sync.aligned.m8n8.x4.trans.shared.b16 {%0,%1,%2,%3}, [%4];" \
                 : "=r"((R)[0]), "=r"((R)[1]), "=r"((R)[2]), "=r"((R)[3]) : "r"(addr))

#define CP16(dst, src) \
    asm volatile("cp.async.ca.shared.global [%0], [%1], 16;" :: "r"(dst), "l"(src))
#define CP_COMMIT() asm volatile("cp.async.commit_group;")
#define CP_WAIT0()  asm volatile("cp.async.wait_group 0;")

__device__ __forceinline__ unsigned su32(const void* p) {
    return (unsigned)__cvta_generic_to_shared(p);
}

// ------------ core mainloop: 64x64 tile, K=256, bf16 k16 mma, ldmatrix frags ------------
// 8 warps as 2(m) x 4(n); warp tile 32x16.
// cr = ar*br + ai*(-bi); ci = ar*bi + ai*br. Accumulate fp32.
__device__ __forceinline__ void mainloop_bf(
    bool gather,
    const bf16* __restrict__ Ar, const bf16* __restrict__ Ai, int lda,
    const bf16* __restrict__ Br, const bf16* __restrict__ Bi, int ldb,
    int m0, int n0, float cr[2][2][4], float ci[2][2][4])
{
    __shared__ __align__(16) bf16 As_r[2][64][40], As_i[2][64][40];   // 32 k + pad 8
    __shared__ __align__(16) bf16 Bs_r[2][32][72], Bs_i[2][32][72];   // 64 n + pad 8
    int tid = threadIdx.x;
    int arw = tid >> 2, ac = (tid & 3) << 3;      // A: 64 rows x 4 chunks (8 bf16)
    int bkr = tid >> 3, bc = (tid & 7) << 3;      // B: 32 k-rows x 8 chunks
    int warp = tid >> 5, lane = tid & 31;
    int wm = (warp & 1) << 5;
    int wn = (warp >> 1) << 4;

    const bf16* ArP = Ar + (size_t)(m0 + arw) * lda + ac;
    const bf16* AiP = Ai + (size_t)(m0 + arw) * lda + ac;
    int bcol = n0 + bc;                            // multiple of 8 -> contiguous in src
    size_t boff = gather ? (size_t)g_map_src[bcol] : (size_t)bcol;
    const bf16* BrP = Br + (size_t)bkr * ldb + boff;
    const bf16* BiP = Bi + (size_t)bkr * ldb + boff;

    // prologue: stage 0 (k chunk 0..31)
    CP16(su32(&As_r[0][arw][ac]), ArP);
    CP16(su32(&As_i[0][arw][ac]), AiP);
    CP16(su32(&Bs_r[0][bkr][bc]), BrP);
    CP16(su32(&Bs_i[0][bkr][bc]), BiP);
    CP_COMMIT();

    // ldmatrix lane addressing
    int alr = lane & 15;                  // A row within 16
    int akoff = (lane >> 4) << 3;         // A k offset 0/8
    int lrow = lane & 15;                 // B k-row
    int lcol = wn + ((lane >> 4) << 3);   // B col

    int p = 0;
    for (int k0 = 0; k0 < 256; k0 += 32) {
        CP_WAIT0();
        __syncthreads();
        if (k0 + 32 < 256) {
            CP16(su32(&As_r[p^1][arw][ac]), ArP + k0 + 32);
            CP16(su32(&As_i[p^1][arw][ac]), AiP + k0 + 32);
            CP16(su32(&Bs_r[p^1][bkr][bc]), BrP + (size_t)(k0 + 32) * ldb);
            CP16(su32(&Bs_i[p^1][bkr][bc]), BiP + (size_t)(k0 + 32) * ldb);
            CP_COMMIT();
        }

#pragma unroll
        for (int ks = 0; ks < 32; ks += 16) {
            unsigned a_r[2][4], a_i[2][4];
#pragma unroll
            for (int ma = 0; ma < 2; ma++) {
                int r0 = wm + ma*16 + alr;
                LDSM4(a_r[ma], su32(&As_r[p][r0][ks + akoff]));
                LDSM4(a_i[ma], su32(&As_i[p][r0][ks + akoff]));
            }
            unsigned b_r[4], b_i[4], b_in[4];
            LDSMT4(b_r, su32(&Bs_r[p][ks + lrow][lcol]));
            LDSMT4(b_i, su32(&Bs_i[p][ks + lrow][lcol]));
#pragma unroll
            for (int q = 0; q < 4; q++) b_in[q] = b_i[q] ^ 0x80008000u;
#pragma unroll
            for (int ma = 0; ma < 2; ma++)
#pragma unroll
                for (int nb = 0; nb < 2; nb++) {
                    MMA16(cr[ma][nb], a_r[ma], (&b_r[nb*2]));
                    MMA16(cr[ma][nb], a_i[ma], (&b_in[nb*2]));
                    MMA16(ci[ma][nb], a_r[ma], (&b_i[nb*2]));
                    MMA16(ci[ma][nb], a_i[ma], (&b_r[nb*2]));
                }
        }
        p ^= 1;
    }
}

// ------------ multi-descriptor GEMM (bf16 in, bf16 out) ------------
struct GemmDesc {
    const bf16 *Ar, *Ai, *Br, *Bi;
    bf16 *Cr, *Ci;
    int lda, ldb, ldc, ntx;   // ntx = N/64
};

__global__ void __launch_bounds__(256, 2)
gemm_multi(GemmDesc da, GemmDesc db, GemmDesc dc, int ca, int cb)
{
    int bx = blockIdx.x;
    GemmDesc d;
    if (bx < ca) d = da;
    else if (bx < ca + cb) { d = db; bx -= ca; }
    else { d = dc; bx -= ca + cb; }
    int tx = bx % d.ntx, ty = bx / d.ntx;
    int m0 = ty * 64, n0 = tx * 64;

    float cr[2][2][4] = {}, ci[2][2][4] = {};
    mainloop_bf(false, d.Ar, d.Ai, d.lda, d.Br, d.Bi, d.ldb, m0, n0, cr, ci);

    int tid = threadIdx.x, warp = tid >> 5, lane = tid & 31;
    int g = lane >> 2, t = lane & 3;
    int wm = (warp & 1) << 5, wn = (warp >> 1) << 4;
#pragma unroll
    for (int ma = 0; ma < 2; ma++)
#pragma unroll
        for (int nb = 0; nb < 2; nb++) {
            int r0 = m0 + wm + ma*16 + g;
            int c0 = n0 + wn + nb*8 + 2*t;
            __nv_bfloat162 v0, v1, w0, w1;
            v0.x = __float2bfloat16(cr[ma][nb][0]); v0.y = __float2bfloat16(cr[ma][nb][1]);
            v1.x = __float2bfloat16(cr[ma][nb][2]); v1.y = __float2bfloat16(cr[ma][nb][3]);
            w0.x = __float2bfloat16(ci[ma][nb][0]); w0.y = __float2bfloat16(ci[ma][nb][1]);
            w1.x = __float2bfloat16(ci[ma][nb][2]); w1.y = __float2bfloat16(ci[ma][nb][3]);
            *(__nv_bfloat162*)&d.Cr[(size_t)r0*d.ldc + c0]     = v0;
            *(__nv_bfloat162*)&d.Cr[(size_t)(r0+8)*d.ldc + c0] = v1;
            *(__nv_bfloat162*)&d.Ci[(size_t)r0*d.ldc + c0]     = w0;
            *(__nv_bfloat162*)&d.Ci[(size_t)(r0+8)*d.ldc + c0] = w1;
        }
}

// ------------ staircase measurement: probs += |G'_ap * W_gathered|^2 ------------
__global__ void __launch_bounds__(256, 2)
measure_mma()
{
    int bx = blockIdx.x;
    int ap = 0;
    while (c_off[ap + 1] <= bx) ap++;
    int n0 = (bx - c_off[ap]) * 64;
    int m0 = blockIdx.y * 64;
    int Neff = 4 * (32 - ap) * (33 - ap);

    float cr[2][2][4] = {}, ci[2][2][4] = {};
    mainloop_bf(true,
                g_G2h_r + (size_t)ap*65536, g_G2h_i + (size_t)ap*65536, 256,
                g_Wh_r, g_Wh_i, 8192, m0, n0, cr, ci);

    int tid = threadIdx.x, warp = tid >> 5, lane = tid & 31;
    int g = lane >> 2, t = lane & 3;
    int wm = (warp & 1) << 5, wn = (warp >> 1) << 4;
    float lb2 = g_lb2;
#pragma unroll
    for (int ma = 0; ma < 2; ma++)
#pragma unroll
        for (int nb = 0; nb < 2; nb++) {
            int r0 = m0 + wm + ma*16 + g;
            int c0 = n0 + wn + nb*8 + 2*t;
#pragma unroll
            for (int jj = 0; jj < 2; jj++) {
                int c = c0 + jj;
                if (c < Neff) {
                    float coef = lb2 * g_gpow[ap + g_map_a[c]];
                    int tb = ap * 8 + g_map_tb[c];
                    float q0 = cr[ma][nb][jj]*cr[ma][nb][jj] + ci[ma][nb][jj]*ci[ma][nb][jj];
                    float q1 = cr[ma][nb][jj+2]*cr[ma][nb][jj+2] + ci[ma][nb][jj+2]*ci[ma][nb][jj+2];
                    atomicAdd(&g_probs[tb*256 + r0],     coef * q0);
                    atomicAdd(&g_probs[tb*256 + r0 + 8], coef * q1);
                }
            }
        }
}

// ------------ MLP head + log_softmax (k-parallel) ------------
__global__ void head(const float* __restrict__ W1, const float* __restrict__ b1,
                     const float* __restrict__ W2, const float* __restrict__ b2,
                     float* __restrict__ out)
{
    int blk = blockIdx.x;        // t*8+b
    int t = blk >> 3, b = blk & 7;
    int tid = threadIdx.x;       // 256
    int j = tid & 63, q = tid >> 6;
    __shared__ float part[4][64];
    __shared__ float h1[64];
    __shared__ float o[6];
    __shared__ float red[2];
    const float* p = g_probs + blk * 256;
    float acc = 0.f;
    int k0 = q * 64;
    for (int k = k0; k < k0 + 64; k++) acc = fmaf(p[k], W1[k*64 + j], acc);
    part[q][j] = acc;
    __syncthreads();
    if (tid < 64) {
        float s = part[0][tid] + part[1][tid] + part[2][tid] + part[3][tid] + b1[tid];
        h1[tid] = fmaxf(s, 0.f);
    }
    __syncthreads();
    if (tid < 6) {
        float a2 = b2[tid];
        for (int qq = 0; qq < 64; qq++) a2 = fmaf(h1[qq], W2[qq*6 + tid], a2);
        o[tid] = tanhf(a2);
    }
    __syncthreads();
    if (tid == 0) {
        float mx = o[0];
        for (int c = 1; c < 6; c++) mx = fmaxf(mx, o[c]);
        float se = 0.f;
        for (int c = 0; c < 6; c++) se += expf(o[c] - mx);
        red[0] = mx; red[1] = logf(se);
    }
    __syncthreads();
    if (tid < 6) out[(b*32 + t)*6 + tid] = o[tid] - red[0] - red[1];
}

// ------------ host helpers ------------
static GemmDesc mk(const bf16* Ar, const bf16* Ai, const bf16* Br, const bf16* Bi,
                   bf16* Cr, bf16* Ci, int lda, int ldb, int ldc, int ntx)
{
    GemmDesc d;
    d.Ar = Ar; d.Ai = Ai; d.Br = Br; d.Bi = Bi; d.Cr = Cr; d.Ci = Ci;
    d.lda = lda; d.ldb = ldb; d.ldc = ldc; d.ntx = ntx;
    return d;
}

// ------------ launch ------------
extern "C" void kernel_launch(void* const* d_in, const int* in_sizes, int n_in,
                              void* d_out, int out_size)
{
    const float* xt    = (const float*)d_in[0];
    const float* xa    = (const float*)d_in[1];
    const float* xv    = (const float*)d_in[2];
    const float* smask = (const float*)d_in[3];
    const float* Wt    = (const float*)d_in[4];
    const float* bt    = (const float*)d_in[5];
    const float* Wa    = (const float*)d_in[6];
    const float* ba    = (const float*)d_in[7];
    const float* Wv    = (const float*)d_in[8];
    const float* bv    = (const float*)d_in[9];
    const float* Pt    = (const float*)d_in[10];
    const float* Pa    = (const float*)d_in[11];
    const float* Pv    = (const float*)d_in[12];
    const float* Uxr   = (const float*)d_in[13];
    const float* Uxi   = (const float*)d_in[14];
    const float* Uhr   = (const float*)d_in[15];
    const float* Uhi   = (const float*)d_in[16];
    const float* Lam   = (const float*)d_in[17];
    const float* Kr    = (const float*)d_in[18];
    const float* Ki    = (const float*)d_in[19];
    const float* W1    = (const float*)d_in[20];
    const float* b1    = (const float*)d_in[21];
    const float* W2    = (const float*)d_in[22];
    const float* b2    = (const float*)d_in[23];
    float* out = (float*)d_out;

    bf16 *Wr, *Wi, *Pr, *Pi, *Gr, *Gi, *G2r, *G2i, *psir, *psii, *Uxhr, *Uxhi, *Uhhr, *Uhhi;
    cudaGetSymbolAddress((void**)&Wr,   g_Wh_r);
    cudaGetSymbolAddress((void**)&Wi,   g_Wh_i);
    cudaGetSymbolAddress((void**)&Pr,   g_Ph_r);
    cudaGetSymbolAddress((void**)&Pi,   g_Ph_i);
    cudaGetSymbolAddress((void**)&Gr,   g_Gh_r);
    cudaGetSymbolAddress((void**)&Gi,   g_Gh_i);
    cudaGetSymbolAddress((void**)&G2r,  g_G2h_r);
    cudaGetSymbolAddress((void**)&G2i,  g_G2h_i);
    cudaGetSymbolAddress((void**)&psir, g_psih_r);
    cudaGetSymbolAddress((void**)&psii, g_psih_i);
    cudaGetSymbolAddress((void**)&Uxhr, g_Uxh_r);
    cudaGetSymbolAddress((void**)&Uxhi, g_Uxh_i);
    cudaGetSymbolAddress((void**)&Uhhr, g_Uhh_r);
    cudaGetSymbolAddress((void**)&Uhhi, g_Uhh_i);

    prep_all<<<785, 256>>>(Lam, xt, xa, xv, smask, Wt, bt, Wa, ba, Wv, bv,
                           Pt, Pa, Pv, Kr, Ki, Uxr, Uxi, Uhr, Uhi);

    // L1: Phi = Ux*Psi -> W[0] | G1 = G0*Uh | P2 = Uh*Uh
    {
        GemmDesc d0 = mk(Uxhr, Uxhi, psir, psii, Wr, Wi, 256, 256, 8192, 4);
        GemmDesc d1 = mk(Gr, Gi, Uhhr, Uhhi, Gr + 65536, Gi + 65536, 256, 256, 256, 4);
        GemmDesc d2 = mk(Uhhr, Uhhi, Uhhr, Uhhi, Pr, Pi, 256, 256, 256, 4);
        gemm_multi<<<48, 256>>>(d0, d1, d2, 16, 16);
    }
    // L2: W1 = Uh*W0 | G[2:4] = G[0:2]*P2 | P4 = P2*P2
    {
        GemmDesc d0 = mk(Uhhr, Uhhi, Wr, Wi, Wr + 256, Wi + 256, 256, 8192, 8192, 4);
        GemmDesc d1 = mk(Gr, Gi, Pr, Pi, Gr + 2*65536, Gi + 2*65536, 256, 256, 256, 4);
        GemmDesc d2 = mk(Pr, Pi, Pr, Pi, Pr + 65536, Pi + 65536, 256, 256, 256, 4);
        gemm_multi<<<64, 256>>>(d0, d1, d2, 16, 32);
    }
    // L3: W[2:4] = P2*W[0:2] | G[4:8] = G[0:4]*P4 | P8 = P4*P4
    {
        GemmDesc d0 = mk(Pr, Pi, Wr, Wi, Wr + 512, Wi + 512, 256, 8192, 8192, 8);
        GemmDesc d1 = mk(Gr, Gi, Pr + 65536, Pi + 65536, Gr + 4*65536, Gi + 4*65536, 256, 256, 256, 4);
        GemmDesc d2 = mk(Pr + 65536, Pi + 65536, Pr + 65536, Pi + 65536, Pr + 131072, Pi + 131072, 256, 256, 256, 4);
        gemm_multi<<<112, 256>>>(d0, d1, d2, 32, 64);
    }
    // L4: W[4:8] = P4*W[0:4] | G[8:16] = G[0:8]*P8 | P16 = P8*P8
    {
        GemmDesc d0 = mk(Pr + 65536, Pi + 65536, Wr, Wi, Wr + 1024, Wi + 1024, 256, 8192, 8192, 16);
        GemmDesc d1 = mk(Gr, Gi, Pr + 131072, Pi + 131072, Gr + 8*65536, Gi + 8*65536, 256, 256, 256, 4);
        GemmDesc d2 = mk(Pr + 131072, Pi + 131072, Pr + 131072, Pi + 131072, Pr + 196608, Pi + 196608, 256, 256, 256, 4);
        gemm_multi<<<208, 256>>>(d0, d1, d2, 64, 128);
    }
    // L5: W[8:16] = P8*W[0:8] | G[16:32] = G[0:16]*P16
    {
        GemmDesc d0 = mk(Pr + 131072, Pi + 131072, Wr, Wi, Wr + 2048, Wi + 2048, 256, 8192, 8192, 32);
        GemmDesc d1 = mk(Gr, Gi, Pr + 196608, Pi + 196608, Gr + 16*65536, Gi + 16*65536, 256, 256, 256, 4);
        gemm_multi<<<384, 256>>>(d0, d1, d0, 128, 256);
    }
    // L6: W[16:32] = P16*W[0:16] | G' = G * Ux (512 blocks: 128 m-tiles x 4 n-tiles)
    {
        GemmDesc d0 = mk(Pr + 196608, Pi + 196608, Wr, Wi, Wr + 4096, Wi + 4096, 256, 8192, 8192, 64);
        GemmDesc d1 = mk(Gr, Gi, Uxhr, Uxhi, G2r, G2i, 256, 256, 256, 4);
        gemm_multi<<<768, 256>>>(d0, d1, d1, 256, 512);
    }

    measure_mma<<<dim3(762, 4), 256>>>();
    head<<<256, 256>>>(W1, b1, W2, b2, out);
}

// round 16
// speedup vs baseline: 1.1454x; 1.1454x over previous
#include <cuda_runtime.h>
#include <cuda_bf16.h>
#include <math.h>

#define Dq    256
#define Bq    8
#define Tq    32
#define NCOLS 256
#define NX    4224
#define BETAq 0.8f

typedef __nv_bfloat16 bf16;

// ------------ device scratch (no allocations) ------------
__device__ __align__(256) bf16 g_psih_r[Dq*NCOLS];
__device__ __align__(256) bf16 g_psih_i[Dq*NCOLS];
__device__ __align__(256) bf16 g_Wh_r[Dq*Tq*256];   // 256 x 8192, ld 8192
__device__ __align__(256) bf16 g_Wh_i[Dq*Tq*256];
__device__ __align__(256) bf16 g_Xh_r[Dq*NX];       // 256 x NX, ld NX (s-sorted contiguous)
__device__ __align__(256) bf16 g_Xh_i[Dq*NX];
__device__ __align__(256) bf16 g_Ph_r[4*Dq*Dq];     // Uh^2, Uh^4, Uh^8, Uh^16
__device__ __align__(256) bf16 g_Ph_i[4*Dq*Dq];
__device__ __align__(256) bf16 g_Gh_r[Tq*256*Dq];   // 8192 x 256, ld 256
__device__ __align__(256) bf16 g_Gh_i[Tq*256*Dq];
__device__ __align__(256) bf16 g_Uxh_r[Dq*Dq], g_Uxh_i[Dq*Dq];
__device__ __align__(256) bf16 g_Uhh_r[Dq*Dq], g_Uhh_i[Dq*Dq];
__device__ __align__(256) float g_probs[Tq*Bq*256]; // (t*8+b)*256 + k
__device__ float g_gpow[64];
__device__ float g_lb2;
__device__ int   g_map_src[NX];
__device__ int   g_map_a[NX];
__device__ int   g_map_tb[NX];

// measure tile prefix offsets: off[ap+1]-off[ap] = ceil(4*(32-ap)*(33-ap)/64)
__constant__ int c_off[33] = {0,66,128,187,242,293,341,385,426,464,499,531,560,587,
                              611,633,653,670,685,699,711,721,730,737,743,748,752,
                              755,757,759,760,761,762};

// ------------ merged prep: maps | psi | norm+probs | convU ------------
__global__ void prep_all(const float* __restrict__ Lambda,
                         const float* __restrict__ xt, const float* __restrict__ xa,
                         const float* __restrict__ xv, const float* __restrict__ smask,
                         const float* __restrict__ Wt, const float* __restrict__ bt,
                         const float* __restrict__ Wa, const float* __restrict__ ba,
                         const float* __restrict__ Wv, const float* __restrict__ bv,
                         const float* __restrict__ Pt, const float* __restrict__ Pa,
                         const float* __restrict__ Pv,
                         const float* __restrict__ Kr, const float* __restrict__ Ki,
                         const float* __restrict__ Uxr, const float* __restrict__ Uxi,
                         const float* __restrict__ Uhr, const float* __restrict__ Uhi)
{
    int bx = blockIdx.x;
    int tid = threadIdx.x;   // 256

    if (bx < 17) {
        // ---- maps + global scalars ----
        if (bx == 0 && tid == 0) {
            float lam = 1.f / (1.f + expf(-Lambda[0]));
            float g = 1.f - lam;
            float p = 1.f;
            for (int i = 0; i < 64; i++) { g_gpow[i] = p; p *= g; }
            g_lb2 = lam * lam * BETAq * BETAq;
        }
        int col = bx * 256 + tid;
        if (col >= NX) return;
        int q = col >> 3, b = col & 7;
        int s = 0;
        while ((s + 1) * (s + 2) / 2 <= q) s++;
        int a = q - s * (s + 1) / 2;
        g_map_src[col] = a * 256 + (s - a) * 8 + b;
        g_map_a[col] = a;
        g_map_tb[col] = s * 8 + b;
        return;
    }

    if (bx < 273) {
        // ---- psi block ----
        int blk = bx - 17;
        int b = blk >> 5, t = blk & 31;
        __shared__ float tr[4], ti[4], ar[8], ai[8], vr[8], vi[8];
        __shared__ float h[8];
        __shared__ int spk;

        if (tid == 0) {
            float s0 = smask[(b*Tq + t)*2 + 0];
            float s1 = smask[(b*Tq + t)*2 + 1];
            spk = (s0 >= s1) ? 0 : 1;
        }
        __syncthreads();

        if (tid < 4) {
            const float* x = xt + (b*Tq + t)*300;
            float acc = bt[tid];
            for (int i = 0; i < 300; i++) acc = fmaf(x[i], Wt[i*4 + tid], acc);
            h[tid] = fmaxf(acc, 0.f);
        }
        __syncthreads();
        if (tid == 0) {
            float n = 0.f;
            for (int j = 0; j < 4; j++) n += h[j]*h[j];
            n = fmaxf(sqrtf(n), 1e-12f);
            for (int j = 0; j < 4; j++) {
                float a = h[j]/n, p = Pt[spk*4 + j];
                tr[j] = a*cosf(p); ti[j] = a*sinf(p);
            }
        }
        __syncthreads();

        if (tid < 8) {
            const float* x = xa + (b*Tq + t)*74;
            float acc = ba[tid];
            for (int i = 0; i < 74; i++) acc = fmaf(x[i], Wa[i*8 + tid], acc);
            h[tid] = fmaxf(acc, 0.f);
        }
        __syncthreads();
        if (tid == 0) {
            float n = 0.f;
            for (int j = 0; j < 8; j++) n += h[j]*h[j];
            n = fmaxf(sqrtf(n), 1e-12f);
            for (int j = 0; j < 8; j++) {
                float a = h[j]/n, p = Pa[spk*8 + j];
                ar[j] = a*cosf(p); ai[j] = a*sinf(p);
            }
        }
        __syncthreads();

        if (tid < 8) {
            const float* x = xv + (b*Tq + t)*35;
            float acc = bv[tid];
            for (int i = 0; i < 35; i++) acc = fmaf(x[i], Wv[i*8 + tid], acc);
            h[tid] = fmaxf(acc, 0.f);
        }
        __syncthreads();
        if (tid == 0) {
            float n = 0.f;
            for (int j = 0; j < 8; j++) n += h[j]*h[j];
            n = fmaxf(sqrtf(n), 1e-12f);
            for (int j = 0; j < 8; j++) {
                float a = h[j]/n, p = Pv[spk*8 + j];
                vr[j] = a*cosf(p); vi[j] = a*sinf(p);
            }
        }
        __syncthreads();

        int col = t*8 + b;
        int idx = tid;
        int it = idx >> 6, ia = (idx >> 3) & 7, iv = idx & 7;
        float pr = tr[it]*ar[ia] - ti[it]*ai[ia];
        float pi = tr[it]*ai[ia] + ti[it]*ar[ia];
        g_psih_r[idx*NCOLS + col] = __float2bfloat16(pr*vr[iv] - pi*vi[iv]);
        g_psih_i[idx*NCOLS + col] = __float2bfloat16(pr*vi[iv] + pi*vr[iv]);
        return;
    }

    if (bx < 529) {
        // ---- norm_m row + probs init ----
        int k = bx - 273;
        __shared__ float red[256];
        float a = Kr[k*256 + tid], c = Ki[k*256 + tid];
        red[tid] = a*a + c*c;
        __syncthreads();
        for (int st = 128; st > 0; st >>= 1) {
            if (tid < st) red[tid] += red[tid + st];
            __syncthreads();
        }
        float inv = 1.f / sqrtf(red[0]);
        g_Gh_r[k*256 + tid] = __float2bfloat16( Kr[k*256 + tid] * inv);
        g_Gh_i[k*256 + tid] = __float2bfloat16(-Ki[k*256 + tid] * inv);
        // probs init: row k of probs -> t = k>>3; compute S locally
        float lam = 1.f / (1.f + expf(-Lambda[0]));
        float g = 1.f - lam;
        int t = k >> 3;
        float gt1 = 1.f;
        for (int i = 0; i <= t; i++) gt1 *= g;
        float S = BETAq * (lam * BETAq * (float)(t + 1) * gt1
                           + (1.f - BETAq) * (1.f - gt1) + gt1) + (1.f - BETAq);
        g_probs[k*256 + tid] = S / 256.f;
        return;
    }

    // ---- convU ----
    int i = (bx - 529) * 256 + tid;
    g_Uxh_r[i] = __float2bfloat16(Uxr[i]);
    g_Uxh_i[i] = __float2bfloat16(Uxi[i]);
    g_Uhh_r[i] = __float2bfloat16(Uhr[i]);
    g_Uhh_i[i] = __float2bfloat16(Uhi[i]);
}

// ------------ bf16 mma + cp.async + ldmatrix helpers ------------
#define MMA16(C, A, B)                                                             \
    asm volatile("mma.sync.aligned.m16n8k16.row.col.f32.bf16.bf16.f32 "           \
                 "{%0,%1,%2,%3},{%4,%5,%6,%7},{%8,%9},{%0,%1,%2,%3};"              \
                 : "+f"((C)[0]), "+f"((C)[1]), "+f"((C)[2]), "+f"((C)[3])          \
                 : "r"((A)[0]), "r"((A)[1]), "r"((A)[2]), "r"((A)[3]),             \
                   "r"((B)[0]), "r"((B)[1]))

#define LDSM4(R, addr) \
    asm volatile("ldmatrix.sync.aligned.m8n8.x4.shared.b16 {%0,%1,%2,%3}, [%4];" \
                 : "=r"((R)[0]), "=r"((R)[1]), "=r"((R)[2]), "=r"((R)[3]) : "r"(addr))

#define LDSMT4(R, addr) \
    asm volatile("ldmatrix.sync.aligned.m8n8.x4.trans.shared.b16 {%0,%1,%2,%3}, [%4];" \
                 : "=r"((R)[0]), "=r"((R)[1]), "=r"((R)[2]), "=r"((R)[3]) : "r"(addr))

#define CP16(dst, src) \
    asm volatile("cp.async.ca.shared.global [%0], [%1], 16;" :: "r"(dst), "l"(src))
#define CP_COMMIT() asm volatile("cp.async.commit_group;")
#define CP_WAIT0()  asm volatile("cp.async.wait_group 0;")

__device__ __forceinline__ unsigned su32(const void* p) {
    return (unsigned)__cvta_generic_to_shared(p);
}

// ------------ core mainloop: 64x64 tile, K=256, bf16 k16 mma, ldmatrix frags ------------
// 8 warps as 2(m) x 4(n); warp tile 32x16.
// cr = ar*br + ai*(-bi); ci = ar*bi + ai*br. Accumulate fp32.
__device__ __forceinline__ void mainloop_bf(
    bool gather,
    const bf16* __restrict__ Ar, const bf16* __restrict__ Ai, int lda,
    const bf16* __restrict__ Br, const bf16* __restrict__ Bi, int ldb,
    int m0, int n0, float cr[2][2][4], float ci[2][2][4])
{
    __shared__ __align__(16) bf16 As_r[2][64][40], As_i[2][64][40];   // 32 k + pad 8
    __shared__ __align__(16) bf16 Bs_r[2][32][72], Bs_i[2][32][72];   // 64 n + pad 8
    int tid = threadIdx.x;
    int arw = tid >> 2, ac = (tid & 3) << 3;      // A: 64 rows x 4 chunks (8 bf16)
    int bkr = tid >> 3, bc = (tid & 7) << 3;      // B: 32 k-rows x 8 chunks
    int warp = tid >> 5, lane = tid & 31;
    int wm = (warp & 1) << 5;
    int wn = (warp >> 1) << 4;

    const bf16* ArP = Ar + (size_t)(m0 + arw) * lda + ac;
    const bf16* AiP = Ai + (size_t)(m0 + arw) * lda + ac;
    int bcol = n0 + bc;                            // multiple of 8 -> contiguous in src
    size_t boff = gather ? (size_t)g_map_src[bcol] : (size_t)bcol;
    const bf16* BrP = Br + (size_t)bkr * ldb + boff;
    const bf16* BiP = Bi + (size_t)bkr * ldb + boff;

    // prologue: stage 0 (k chunk 0..31)
    CP16(su32(&As_r[0][arw][ac]), ArP);
    CP16(su32(&As_i[0][arw][ac]), AiP);
    CP16(su32(&Bs_r[0][bkr][bc]), BrP);
    CP16(su32(&Bs_i[0][bkr][bc]), BiP);
    CP_COMMIT();

    // ldmatrix lane addressing
    int alr = lane & 15;                  // A row within 16
    int akoff = (lane >> 4) << 3;         // A k offset 0/8
    int lrow = lane & 15;                 // B k-row
    int lcol = wn + ((lane >> 4) << 3);   // B col

    int p = 0;
    for (int k0 = 0; k0 < 256; k0 += 32) {
        CP_WAIT0();
        __syncthreads();
        if (k0 + 32 < 256) {
            CP16(su32(&As_r[p^1][arw][ac]), ArP + k0 + 32);
            CP16(su32(&As_i[p^1][arw][ac]), AiP + k0 + 32);
            CP16(su32(&Bs_r[p^1][bkr][bc]), BrP + (size_t)(k0 + 32) * ldb);
            CP16(su32(&Bs_i[p^1][bkr][bc]), BiP + (size_t)(k0 + 32) * ldb);
            CP_COMMIT();
        }

#pragma unroll
        for (int ks = 0; ks < 32; ks += 16) {
            unsigned a_r[2][4], a_i[2][4];
#pragma unroll
            for (int ma = 0; ma < 2; ma++) {
                int r0 = wm + ma*16 + alr;
                LDSM4(a_r[ma], su32(&As_r[p][r0][ks + akoff]));
                LDSM4(a_i[ma], su32(&As_i[p][r0][ks + akoff]));
            }
            unsigned b_r[4], b_i[4], b_in[4];
            LDSMT4(b_r, su32(&Bs_r[p][ks + lrow][lcol]));
            LDSMT4(b_i, su32(&Bs_i[p][ks + lrow][lcol]));
#pragma unroll
            for (int q = 0; q < 4; q++) b_in[q] = b_i[q] ^ 0x80008000u;
#pragma unroll
            for (int ma = 0; ma < 2; ma++)
#pragma unroll
                for (int nb = 0; nb < 2; nb++) {
                    MMA16(cr[ma][nb], a_r[ma], (&b_r[nb*2]));
                    MMA16(cr[ma][nb], a_i[ma], (&b_in[nb*2]));
                    MMA16(ci[ma][nb], a_r[ma], (&b_i[nb*2]));
                    MMA16(ci[ma][nb], a_i[ma], (&b_r[nb*2]));
                }
        }
        p ^= 1;
    }
}

// ------------ multi-descriptor GEMM (bf16 in, bf16 out) ------------
struct GemmDesc {
    const bf16 *Ar, *Ai, *Br, *Bi;
    bf16 *Cr, *Ci;
    int lda, ldb, ldc, ntx;   // ntx = N/64
};

__global__ void __launch_bounds__(256, 2)
gemm_multi(GemmDesc da, GemmDesc db, GemmDesc dc, int ca, int cb)
{
    int bx = blockIdx.x;
    GemmDesc d;
    if (bx < ca) d = da;
    else if (bx < ca + cb) { d = db; bx -= ca; }
    else { d = dc; bx -= ca + cb; }
    int tx = bx % d.ntx, ty = bx / d.ntx;
    int m0 = ty * 64, n0 = tx * 64;

    float cr[2][2][4] = {}, ci[2][2][4] = {};
    mainloop_bf(false, d.Ar, d.Ai, d.lda, d.Br, d.Bi, d.ldb, m0, n0, cr, ci);

    int tid = threadIdx.x, warp = tid >> 5, lane = tid & 31;
    int g = lane >> 2, t = lane & 3;
    int wm = (warp & 1) << 5, wn = (warp >> 1) << 4;
#pragma unroll
    for (int ma = 0; ma < 2; ma++)
#pragma unroll
        for (int nb = 0; nb < 2; nb++) {
            int r0 = m0 + wm + ma*16 + g;
            int c0 = n0 + wn + nb*8 + 2*t;
            __nv_bfloat162 v0, v1, w0, w1;
            v0.x = __float2bfloat16(cr[ma][nb][0]); v0.y = __float2bfloat16(cr[ma][nb][1]);
            v1.x = __float2bfloat16(cr[ma][nb][2]); v1.y = __float2bfloat16(cr[ma][nb][3]);
            w0.x = __float2bfloat16(ci[ma][nb][0]); w0.y = __float2bfloat16(ci[ma][nb][1]);
            w1.x = __float2bfloat16(ci[ma][nb][2]); w1.y = __float2bfloat16(ci[ma][nb][3]);
            *(__nv_bfloat162*)&d.Cr[(size_t)r0*d.ldc + c0]     = v0;
            *(__nv_bfloat162*)&d.Cr[(size_t)(r0+8)*d.ldc + c0] = v1;
            *(__nv_bfloat162*)&d.Ci[(size_t)r0*d.ldc + c0]     = w0;
            *(__nv_bfloat162*)&d.Ci[(size_t)(r0+8)*d.ldc + c0] = w1;
        }
}

// ------------ X = Ux * gathered(W), bf16 out ------------
__global__ void __launch_bounds__(256, 2)
gemm_gatherX()
{
    int m0 = blockIdx.y * 64, n0 = blockIdx.x * 64;
    float cr[2][2][4] = {}, ci[2][2][4] = {};
    mainloop_bf(true, g_Uxh_r, g_Uxh_i, 256, g_Wh_r, g_Wh_i, 8192, m0, n0, cr, ci);

    int tid = threadIdx.x, warp = tid >> 5, lane = tid & 31;
    int g = lane >> 2, t = lane & 3;
    int wm = (warp & 1) << 5, wn = (warp >> 1) << 4;
#pragma unroll
    for (int ma = 0; ma < 2; ma++)
#pragma unroll
        for (int nb = 0; nb < 2; nb++) {
            int r0 = m0 + wm + ma*16 + g;
            int c0 = n0 + wn + nb*8 + 2*t;
            __nv_bfloat162 v0, v1, w0, w1;
            v0.x = __float2bfloat16(cr[ma][nb][0]); v0.y = __float2bfloat16(cr[ma][nb][1]);
            v1.x = __float2bfloat16(cr[ma][nb][2]); v1.y = __float2bfloat16(cr[ma][nb][3]);
            w0.x = __float2bfloat16(ci[ma][nb][0]); w0.y = __float2bfloat16(ci[ma][nb][1]);
            w1.x = __float2bfloat16(ci[ma][nb][2]); w1.y = __float2bfloat16(ci[ma][nb][3]);
            *(__nv_bfloat162*)&g_Xh_r[(size_t)r0*NX + c0]     = v0;
            *(__nv_bfloat162*)&g_Xh_r[(size_t)(r0+8)*NX + c0] = v1;
            *(__nv_bfloat162*)&g_Xh_i[(size_t)r0*NX + c0]     = w0;
            *(__nv_bfloat162*)&g_Xh_i[(size_t)(r0+8)*NX + c0] = w1;
        }
}

// ------------ staircase measurement (flat grid, bf16 mma, fp32 epilogue) ------------
__global__ void __launch_bounds__(256, 2)
measure_mma()
{
    int bx = blockIdx.x;
    int ap = 0;
    while (c_off[ap + 1] <= bx) ap++;
    int n0 = (bx - c_off[ap]) * 64;
    int m0 = blockIdx.y * 64;
    int Neff = 4 * (32 - ap) * (33 - ap);

    float cr[2][2][4] = {}, ci[2][2][4] = {};
    mainloop_bf(false,
                g_Gh_r + (size_t)ap*65536, g_Gh_i + (size_t)ap*65536, 256,
                g_Xh_r, g_Xh_i, NX, m0, n0, cr, ci);

    int tid = threadIdx.x, warp = tid >> 5, lane = tid & 31;
    int g = lane >> 2, t = lane & 3;
    int wm = (warp & 1) << 5, wn = (warp >> 1) << 4;
    float lb2 = g_lb2;
#pragma unroll
    for (int ma = 0; ma < 2; ma++)
#pragma unroll
        for (int nb = 0; nb < 2; nb++) {
            int r0 = m0 + wm + ma*16 + g;
            int c0 = n0 + wn + nb*8 + 2*t;
#pragma unroll
            for (int jj = 0; jj < 2; jj++) {
                int c = c0 + jj;
                if (c < Neff) {
                    float coef = lb2 * g_gpow[ap + g_map_a[c]];
                    int tb = ap * 8 + g_map_tb[c];
                    float q0 = cr[ma][nb][jj]*cr[ma][nb][jj] + ci[ma][nb][jj]*ci[ma][nb][jj];
                    float q1 = cr[ma][nb][jj+2]*cr[ma][nb][jj+2] + ci[ma][nb][jj+2]*ci[ma][nb][jj+2];
                    atomicAdd(&g_probs[tb*256 + r0],     coef * q0);
                    atomicAdd(&g_probs[tb*256 + r0 + 8], coef * q1);
                }
            }
        }
}

// ------------ MLP head + log_softmax (k-parallel) ------------
__global__ void head(const float* __restrict__ W1, const float* __restrict__ b1,
                     const float* __restrict__ W2, const float* __restrict__ b2,
                     float* __restrict__ out)
{
    int blk = blockIdx.x;        // t*8+b
    int t = blk >> 3, b = blk & 7;
    int tid = threadIdx.x;       // 256
    int j = tid & 63, q = tid >> 6;
    __shared__ float part[4][64];
    __shared__ float h1[64];
    __shared__ float o[6];
    __shared__ float red[2];
    const float* p = g_probs + blk * 256;
    float acc = 0.f;
    int k0 = q * 64;
    for (int k = k0; k < k0 + 64; k++) acc = fmaf(p[k], W1[k*64 + j], acc);
    part[q][j] = acc;
    __syncthreads();
    if (tid < 64) {
        float s = part[0][tid] + part[1][tid] + part[2][tid] + part[3][tid] + b1[tid];
        h1[tid] = fmaxf(s, 0.f);
    }
    __syncthreads();
    if (tid < 6) {
        float a2 = b2[tid];
        for (int qq = 0; qq < 64; qq++) a2 = fmaf(h1[qq], W2[qq*6 + tid], a2);
        o[tid] = tanhf(a2);
    }
    __syncthreads();
    if (tid == 0) {
        float mx = o[0];
        for (int c = 1; c < 6; c++) mx = fmaxf(mx, o[c]);
        float se = 0.f;
        for (int c = 0; c < 6; c++) se += expf(o[c] - mx);
        red[0] = mx; red[1] = logf(se);
    }
    __syncthreads();
    if (tid < 6) out[(b*32 + t)*6 + tid] = o[tid] - red[0] - red[1];
}

// ------------ host helpers ------------
static GemmDesc mk(const bf16* Ar, const bf16* Ai, const bf16* Br, const bf16* Bi,
                   bf16* Cr, bf16* Ci, int lda, int ldb, int ldc, int ntx)
{
    GemmDesc d;
    d.Ar = Ar; d.Ai = Ai; d.Br = Br; d.Bi = Bi; d.Cr = Cr; d.Ci = Ci;
    d.lda = lda; d.ldb = ldb; d.ldc = ldc; d.ntx = ntx;
    return d;
}

// ------------ launch ------------
extern "C" void kernel_launch(void* const* d_in, const int* in_sizes, int n_in,
                              void* d_out, int out_size)
{
    const float* xt    = (const float*)d_in[0];
    const float* xa    = (const float*)d_in[1];
    const float* xv    = (const float*)d_in[2];
    const float* smask = (const float*)d_in[3];
    const float* Wt    = (const float*)d_in[4];
    const float* bt    = (const float*)d_in[5];
    const float* Wa    = (const float*)d_in[6];
    const float* ba    = (const float*)d_in[7];
    const float* Wv    = (const float*)d_in[8];
    const float* bv    = (const float*)d_in[9];
    const float* Pt    = (const float*)d_in[10];
    const float* Pa    = (const float*)d_in[11];
    const float* Pv    = (const float*)d_in[12];
    const float* Uxr   = (const float*)d_in[13];
    const float* Uxi   = (const float*)d_in[14];
    const float* Uhr   = (const float*)d_in[15];
    const float* Uhi   = (const float*)d_in[16];
    const float* Lam   = (const float*)d_in[17];
    const float* Kr    = (const float*)d_in[18];
    const float* Ki    = (const float*)d_in[19];
    const float* W1    = (const float*)d_in[20];
    const float* b1    = (const float*)d_in[21];
    const float* W2    = (const float*)d_in[22];
    const float* b2    = (const float*)d_in[23];
    float* out = (float*)d_out;

    bf16 *Wr, *Wi, *Pr, *Pi, *Gr, *Gi, *psir, *psii, *Uxhr, *Uxhi, *Uhhr, *Uhhi;
    cudaGetSymbolAddress((void**)&Wr,   g_Wh_r);
    cudaGetSymbolAddress((void**)&Wi,   g_Wh_i);
    cudaGetSymbolAddress((void**)&Pr,   g_Ph_r);
    cudaGetSymbolAddress((void**)&Pi,   g_Ph_i);
    cudaGetSymbolAddress((void**)&Gr,   g_Gh_r);
    cudaGetSymbolAddress((void**)&Gi,   g_Gh_i);
    cudaGetSymbolAddress((void**)&psir, g_psih_r);
    cudaGetSymbolAddress((void**)&psii, g_psih_i);
    cudaGetSymbolAddress((void**)&Uxhr, g_Uxh_r);
    cudaGetSymbolAddress((void**)&Uxhi, g_Uxh_i);
    cudaGetSymbolAddress((void**)&Uhhr, g_Uhh_r);
    cudaGetSymbolAddress((void**)&Uhhi, g_Uhh_i);

    prep_all<<<785, 256>>>(Lam, xt, xa, xv, smask, Wt, bt, Wa, ba, Wv, bv,
                           Pt, Pa, Pv, Kr, Ki, Uxr, Uxi, Uhr, Uhi);

    // L1: Phi = Ux*Psi -> W[0] | G1 = G0*Uh | P2 = Uh*Uh
    {
        GemmDesc d0 = mk(Uxhr, Uxhi, psir, psii, Wr, Wi, 256, 256, 8192, 4);
        GemmDesc d1 = mk(Gr, Gi, Uhhr, Uhhi, Gr + 65536, Gi + 65536, 256, 256, 256, 4);
        GemmDesc d2 = mk(Uhhr, Uhhi, Uhhr, Uhhi, Pr, Pi, 256, 256, 256, 4);
        gemm_multi<<<48, 256>>>(d0, d1, d2, 16, 16);
    }
    // L2: W1 = Uh*W0 | G[2:4] = G[0:2]*P2 | P4 = P2*P2
    {
        GemmDesc d0 = mk(Uhhr, Uhhi, Wr, Wi, Wr + 256, Wi + 256, 256, 8192, 8192, 4);
        GemmDesc d1 = mk(Gr, Gi, Pr, Pi, Gr + 2*65536, Gi + 2*65536, 256, 256, 256, 4);
        GemmDesc d2 = mk(Pr, Pi, Pr, Pi, Pr + 65536, Pi + 65536, 256, 256, 256, 4);
        gemm_multi<<<64, 256>>>(d0, d1, d2, 16, 32);
    }
    // L3: W[2:4] = P2*W[0:2] | G[4:8] = G[0:4]*P4 | P8 = P4*P4
    {
        GemmDesc d0 = mk(Pr, Pi, Wr, Wi, Wr + 512, Wi + 512, 256, 8192, 8192, 8);
        GemmDesc d1 = mk(Gr, Gi, Pr + 65536, Pi + 65536, Gr + 4*65536, Gi + 4*65536, 256, 256, 256, 4);
        GemmDesc d2 = mk(Pr + 65536, Pi + 65536, Pr + 65536, Pi + 65536, Pr + 131072, Pi + 131072, 256, 256, 256, 4);
        gemm_multi<<<112, 256>>>(d0, d1, d2, 32, 64);
    }
    // L4: W[4:8] = P4*W[0:4] | G[8:16] = G[0:8]*P8 | P16 = P8*P8
    {
        GemmDesc d0 = mk(Pr + 65536, Pi + 65536, Wr, Wi, Wr + 1024, Wi + 1024, 256, 8192, 8192, 16);
        GemmDesc d1 = mk(Gr, Gi, Pr + 131072, Pi + 131072, Gr + 8*65536, Gi + 8*65536, 256, 256, 256, 4);
        GemmDesc d2 = mk(Pr + 131072, Pi + 131072, Pr + 131072, Pi + 131072, Pr + 196608, Pi + 196608, 256, 256, 256, 4);
        gemm_multi<<<208, 256>>>(d0, d1, d2, 64, 128);
    }
    // L5: W[8:16] = P8*W[0:8] | G[16:32] = G[0:16]*P16
    {
        GemmDesc d0 = mk(Pr + 131072, Pi + 131072, Wr, Wi, Wr + 2048, Wi + 2048, 256, 8192, 8192, 32);
        GemmDesc d1 = mk(Gr, Gi, Pr + 196608, Pi + 196608, Gr + 16*65536, Gi + 16*65536, 256, 256, 256, 4);
        gemm_multi<<<384, 256>>>(d0, d1, d0, 128, 256);
    }
    // L6: W[16:32] = P16*W[0:16]
    {
        GemmDesc d0 = mk(Pr + 196608, Pi + 196608, Wr, Wi, Wr + 4096, Wi + 4096, 256, 8192, 8192, 64);
        gemm_multi<<<256, 256>>>(d0, d0, d0, 256, 0);
    }
    // X = Ux * gathered(W)
    gemm_gatherX<<<dim3(66, 4), 256>>>();

    measure_mma<<<dim3(762, 4), 256>>>();
    head<<<256, 256>>>(W1, b1, W2, b2, out);
}

// round 17
// speedup vs baseline: 1.2440x; 1.0861x over previous
#include <cuda_runtime.h>
#include <cuda_bf16.h>
#include <math.h>

#define Dq    256
#define Bq    8
#define Tq    32
#define NCOLS 256
#define NX    4224
#define BETAq 0.8f

typedef __nv_bfloat16 bf16;

// ------------ device scratch (no allocations) ------------
__device__ __align__(256) bf16 g_psih_r[Dq*NCOLS];
__device__ __align__(256) bf16 g_psih_i[Dq*NCOLS];
__device__ __align__(256) bf16 g_Wh_r[Dq*Tq*256];   // 256 x 8192, ld 8192
__device__ __align__(256) bf16 g_Wh_i[Dq*Tq*256];
__device__ __align__(256) bf16 g_Xh_r[Dq*NX];       // 256 x NX, ld NX (s-sorted contiguous)
__device__ __align__(256) bf16 g_Xh_i[Dq*NX];
__device__ __align__(256) bf16 g_Ph_r[4*Dq*Dq];     // Uh^2, Uh^4, Uh^8, Uh^16
__device__ __align__(256) bf16 g_Ph_i[4*Dq*Dq];
__device__ __align__(256) bf16 g_Gh_r[Tq*256*Dq];   // 8192 x 256, ld 256
__device__ __align__(256) bf16 g_Gh_i[Tq*256*Dq];
__device__ __align__(256) bf16 g_Uxh_r[Dq*Dq], g_Uxh_i[Dq*Dq];
__device__ __align__(256) bf16 g_Uhh_r[Dq*Dq], g_Uhh_i[Dq*Dq];
__device__ __align__(256) float g_probs[Tq*Bq*256]; // (t*8+b)*256 + k
__device__ float g_gpow[64];
__device__ float g_lb2;
__device__ int   g_map_src[NX];
__device__ int   g_map_a[NX];
__device__ int   g_map_tb[NX];

// measure tile prefix offsets: off[ap+1]-off[ap] = ceil(4*(32-ap)*(33-ap)/64)
__constant__ int c_off[33] = {0,66,128,187,242,293,341,385,426,464,499,531,560,587,
                              611,633,653,670,685,699,711,721,730,737,743,748,752,
                              755,757,759,760,761,762};

// dynamic smem layout (elements of bf16), 3 stages:
//   As_r: [3][64][40] @ 0          (stage stride 2560)
//   As_i: [3][64][40] @ 7680
//   Bs_r: [3][32][72] @ 15360      (stage stride 2304)
//   Bs_i: [3][32][72] @ 22272
// total 29184 bf16 = 58368 bytes
#define SMEM_BYTES 58368
#define ASR(st,r,c) dsm[(st)*2560 + (r)*40 + (c)]
#define ASI(st,r,c) dsm[7680 + (st)*2560 + (r)*40 + (c)]
#define BSR(st,r,c) dsm[15360 + (st)*2304 + (r)*72 + (c)]
#define BSI(st,r,c) dsm[22272 + (st)*2304 + (r)*72 + (c)]

// ------------ merged prep: maps | psi | norm+probs | convU ------------
__global__ void prep_all(const float* __restrict__ Lambda,
                         const float* __restrict__ xt, const float* __restrict__ xa,
                         const float* __restrict__ xv, const float* __restrict__ smask,
                         const float* __restrict__ Wt, const float* __restrict__ bt,
                         const float* __restrict__ Wa, const float* __restrict__ ba,
                         const float* __restrict__ Wv, const float* __restrict__ bv,
                         const float* __restrict__ Pt, const float* __restrict__ Pa,
                         const float* __restrict__ Pv,
                         const float* __restrict__ Kr, const float* __restrict__ Ki,
                         const float* __restrict__ Uxr, const float* __restrict__ Uxi,
                         const float* __restrict__ Uhr, const float* __restrict__ Uhi)
{
    int bx = blockIdx.x;
    int tid = threadIdx.x;   // 256

    if (bx < 17) {
        if (bx == 0 && tid == 0) {
            float lam = 1.f / (1.f + expf(-Lambda[0]));
            float g = 1.f - lam;
            float p = 1.f;
            for (int i = 0; i < 64; i++) { g_gpow[i] = p; p *= g; }
            g_lb2 = lam * lam * BETAq * BETAq;
        }
        int col = bx * 256 + tid;
        if (col >= NX) return;
        int q = col >> 3, b = col & 7;
        int s = 0;
        while ((s + 1) * (s + 2) / 2 <= q) s++;
        int a = q - s * (s + 1) / 2;
        g_map_src[col] = a * 256 + (s - a) * 8 + b;
        g_map_a[col] = a;
        g_map_tb[col] = s * 8 + b;
        return;
    }

    if (bx < 273) {
        int blk = bx - 17;
        int b = blk >> 5, t = blk & 31;
        __shared__ float tr[4], ti[4], ar[8], ai[8], vr[8], vi[8];
        __shared__ float h[8];
        __shared__ int spk;

        if (tid == 0) {
            float s0 = smask[(b*Tq + t)*2 + 0];
            float s1 = smask[(b*Tq + t)*2 + 1];
            spk = (s0 >= s1) ? 0 : 1;
        }
        __syncthreads();

        if (tid < 4) {
            const float* x = xt + (b*Tq + t)*300;
            float acc = bt[tid];
            for (int i = 0; i < 300; i++) acc = fmaf(x[i], Wt[i*4 + tid], acc);
            h[tid] = fmaxf(acc, 0.f);
        }
        __syncthreads();
        if (tid == 0) {
            float n = 0.f;
            for (int j = 0; j < 4; j++) n += h[j]*h[j];
            n = fmaxf(sqrtf(n), 1e-12f);
            for (int j = 0; j < 4; j++) {
                float a = h[j]/n, p = Pt[spk*4 + j];
                tr[j] = a*cosf(p); ti[j] = a*sinf(p);
            }
        }
        __syncthreads();

        if (tid < 8) {
            const float* x = xa + (b*Tq + t)*74;
            float acc = ba[tid];
            for (int i = 0; i < 74; i++) acc = fmaf(x[i], Wa[i*8 + tid], acc);
            h[tid] = fmaxf(acc, 0.f);
        }
        __syncthreads();
        if (tid == 0) {
            float n = 0.f;
            for (int j = 0; j < 8; j++) n += h[j]*h[j];
            n = fmaxf(sqrtf(n), 1e-12f);
            for (int j = 0; j < 8; j++) {
                float a = h[j]/n, p = Pa[spk*8 + j];
                ar[j] = a*cosf(p); ai[j] = a*sinf(p);
            }
        }
        __syncthreads();

        if (tid < 8) {
            const float* x = xv + (b*Tq + t)*35;
            float acc = bv[tid];
            for (int i = 0; i < 35; i++) acc = fmaf(x[i], Wv[i*8 + tid], acc);
            h[tid] = fmaxf(acc, 0.f);
        }
        __syncthreads();
        if (tid == 0) {
            float n = 0.f;
            for (int j = 0; j < 8; j++) n += h[j]*h[j];
            n = fmaxf(sqrtf(n), 1e-12f);
            for (int j = 0; j < 8; j++) {
                float a = h[j]/n, p = Pv[spk*8 + j];
                vr[j] = a*cosf(p); vi[j] = a*sinf(p);
            }
        }
        __syncthreads();

        int col = t*8 + b;
        int idx = tid;
        int it = idx >> 6, ia = (idx >> 3) & 7, iv = idx & 7;
        float pr = tr[it]*ar[ia] - ti[it]*ai[ia];
        float pi = tr[it]*ai[ia] + ti[it]*ar[ia];
        g_psih_r[idx*NCOLS + col] = __float2bfloat16(pr*vr[iv] - pi*vi[iv]);
        g_psih_i[idx*NCOLS + col] = __float2bfloat16(pr*vi[iv] + pi*vr[iv]);
        return;
    }

    if (bx < 529) {
        int k = bx - 273;
        __shared__ float red[256];
        float a = Kr[k*256 + tid], c = Ki[k*256 + tid];
        red[tid] = a*a + c*c;
        __syncthreads();
        for (int st = 128; st > 0; st >>= 1) {
            if (tid < st) red[tid] += red[tid + st];
            __syncthreads();
        }
        float inv = 1.f / sqrtf(red[0]);
        g_Gh_r[k*256 + tid] = __float2bfloat16( Kr[k*256 + tid] * inv);
        g_Gh_i[k*256 + tid] = __float2bfloat16(-Ki[k*256 + tid] * inv);
        float lam = 1.f / (1.f + expf(-Lambda[0]));
        float g = 1.f - lam;
        int t = k >> 3;
        float gt1 = 1.f;
        for (int i = 0; i <= t; i++) gt1 *= g;
        float S = BETAq * (lam * BETAq * (float)(t + 1) * gt1
                           + (1.f - BETAq) * (1.f - gt1) + gt1) + (1.f - BETAq);
        g_probs[k*256 + tid] = S / 256.f;
        return;
    }

    int i = (bx - 529) * 256 + tid;
    g_Uxh_r[i] = __float2bfloat16(Uxr[i]);
    g_Uxh_i[i] = __float2bfloat16(Uxi[i]);
    g_Uhh_r[i] = __float2bfloat16(Uhr[i]);
    g_Uhh_i[i] = __float2bfloat16(Uhi[i]);
}

// ------------ bf16 mma + cp.async + ldmatrix helpers ------------
#define MMA16(C, A, B)                                                             \
    asm volatile("mma.sync.aligned.m16n8k16.row.col.f32.bf16.bf16.f32 "           \
                 "{%0,%1,%2,%3},{%4,%5,%6,%7},{%8,%9},{%0,%1,%2,%3};"              \
                 : "+f"((C)[0]), "+f"((C)[1]), "+f"((C)[2]), "+f"((C)[3])          \
                 : "r"((A)[0]), "r"((A)[1]), "r"((A)[2]), "r"((A)[3]),             \
                   "r"((B)[0]), "r"((B)[1]))

#define LDSM4(R, addr) \
    asm volatile("ldmatrix.sync.aligned.m8n8.x4.shared.b16 {%0,%1,%2,%3}, [%4];" \
                 : "=r"((R)[0]), "=r"((R)[1]), "=r"((R)[2]), "=r"((R)[3]) : "r"(addr))

#define LDSMT4(R, addr) \
    asm volatile("ldmatrix.sync.aligned.m8n8.x4.trans.shared.b16 {%0,%1,%2,%3}, [%4];" \
                 : "=r"((R)[0]), "=r"((R)[1]), "=r"((R)[2]), "=r"((R)[3]) : "r"(addr))

#define CP16(dst, src) \
    asm volatile("cp.async.ca.shared.global [%0], [%1], 16;" :: "r"(dst), "l"(src))
#define CP_COMMIT() asm volatile("cp.async.commit_group;")
#define CP_WAIT0()  asm volatile("cp.async.wait_group 0;")
#define CP_WAIT1()  asm volatile("cp.async.wait_group 1;")

__device__ __forceinline__ unsigned su32(const void* p) {
    return (unsigned)__cvta_generic_to_shared(p);
}

// ------------ core mainloop: 64x64 tile, K=256, bf16 k16 mma, 3-stage cp.async ------------
// 8 warps as 2(m) x 4(n); warp tile 32x16.
// cr = ar*br + ai*(-bi); ci = ar*bi + ai*br. Accumulate fp32.
__device__ __forceinline__ void mainloop_bf(
    bool gather,
    const bf16* __restrict__ Ar, const bf16* __restrict__ Ai, int lda,
    const bf16* __restrict__ Br, const bf16* __restrict__ Bi, int ldb,
    int m0, int n0, float cr[2][2][4], float ci[2][2][4])
{
    extern __shared__ bf16 dsm[];
    int tid = threadIdx.x;
    int arw = tid >> 2, ac = (tid & 3) << 3;      // A: 64 rows x 4 chunks (8 bf16)
    int bkr = tid >> 3, bc = (tid & 7) << 3;      // B: 32 k-rows x 8 chunks
    int warp = tid >> 5, lane = tid & 31;
    int wm = (warp & 1) << 5;
    int wn = (warp >> 1) << 4;

    const bf16* ArP = Ar + (size_t)(m0 + arw) * lda + ac;
    const bf16* AiP = Ai + (size_t)(m0 + arw) * lda + ac;
    int bcol = n0 + bc;                            // multiple of 8 -> contiguous in src
    size_t boff = gather ? (size_t)g_map_src[bcol] : (size_t)bcol;
    const bf16* BrP = Br + (size_t)bkr * ldb + boff;
    const bf16* BiP = Bi + (size_t)bkr * ldb + boff;

    // prologue: issue stages 0 and 1 (chunks 0 and 1)
    CP16(su32(&ASR(0, arw, ac)), ArP);
    CP16(su32(&ASI(0, arw, ac)), AiP);
    CP16(su32(&BSR(0, bkr, bc)), BrP);
    CP16(su32(&BSI(0, bkr, bc)), BiP);
    CP_COMMIT();
    CP16(su32(&ASR(1, arw, ac)), ArP + 32);
    CP16(su32(&ASI(1, arw, ac)), AiP + 32);
    CP16(su32(&BSR(1, bkr, bc)), BrP + (size_t)32 * ldb);
    CP16(su32(&BSI(1, bkr, bc)), BiP + (size_t)32 * ldb);
    CP_COMMIT();

    // ldmatrix lane addressing
    int alr = lane & 15;                  // A row within 16
    int akoff = (lane >> 4) << 3;         // A k offset 0/8
    int lrow = lane & 15;                 // B k-row
    int lcol = wn + ((lane >> 4) << 3);   // B col

#pragma unroll
    for (int ch = 0; ch < 8; ch++) {
        if (ch >= 6) CP_WAIT0(); else CP_WAIT1();   // drain exactly to chunk ch
        __syncthreads();
        if (ch + 2 < 8) {
            int st = (ch + 2) % 3;
            int kf = (ch + 2) * 32;
            CP16(su32(&ASR(st, arw, ac)), ArP + kf);
            CP16(su32(&ASI(st, arw, ac)), AiP + kf);
            CP16(su32(&BSR(st, bkr, bc)), BrP + (size_t)kf * ldb);
            CP16(su32(&BSI(st, bkr, bc)), BiP + (size_t)kf * ldb);
            CP_COMMIT();
        }
        int p = ch % 3;

#pragma unroll
        for (int ks = 0; ks < 32; ks += 16) {
            unsigned a_r[2][4], a_i[2][4];
#pragma unroll
            for (int ma = 0; ma < 2; ma++) {
                int r0 = wm + ma*16 + alr;
                LDSM4(a_r[ma], su32(&ASR(p, r0, ks + akoff)));
                LDSM4(a_i[ma], su32(&ASI(p, r0, ks + akoff)));
            }
            unsigned b_r[4], b_i[4], b_in[4];
            LDSMT4(b_r, su32(&BSR(p, ks + lrow, lcol)));
            LDSMT4(b_i, su32(&BSI(p, ks + lrow, lcol)));
#pragma unroll
            for (int q = 0; q < 4; q++) b_in[q] = b_i[q] ^ 0x80008000u;
#pragma unroll
            for (int ma = 0; ma < 2; ma++)
#pragma unroll
                for (int nb = 0; nb < 2; nb++) {
                    MMA16(cr[ma][nb], a_r[ma], (&b_r[nb*2]));
                    MMA16(cr[ma][nb], a_i[ma], (&b_in[nb*2]));
                    MMA16(ci[ma][nb], a_r[ma], (&b_i[nb*2]));
                    MMA16(ci[ma][nb], a_i[ma], (&b_r[nb*2]));
                }
        }
    }
}

// ------------ multi-descriptor GEMM (bf16 in, bf16 out) ------------
struct GemmDesc {
    const bf16 *Ar, *Ai, *Br, *Bi;
    bf16 *Cr, *Ci;
    int lda, ldb, ldc, ntx;   // ntx = N/64
};

__global__ void __launch_bounds__(256, 2)
gemm_multi(GemmDesc da, GemmDesc db, GemmDesc dc, int ca, int cb)
{
    int bx = blockIdx.x;
    GemmDesc d;
    if (bx < ca) d = da;
    else if (bx < ca + cb) { d = db; bx -= ca; }
    else { d = dc; bx -= ca + cb; }
    int tx = bx % d.ntx, ty = bx / d.ntx;
    int m0 = ty * 64, n0 = tx * 64;

    float cr[2][2][4] = {}, ci[2][2][4] = {};
    mainloop_bf(false, d.Ar, d.Ai, d.lda, d.Br, d.Bi, d.ldb, m0, n0, cr, ci);

    int tid = threadIdx.x, warp = tid >> 5, lane = tid & 31;
    int g = lane >> 2, t = lane & 3;
    int wm = (warp & 1) << 5, wn = (warp >> 1) << 4;
#pragma unroll
    for (int ma = 0; ma < 2; ma++)
#pragma unroll
        for (int nb = 0; nb < 2; nb++) {
            int r0 = m0 + wm + ma*16 + g;
            int c0 = n0 + wn + nb*8 + 2*t;
            __nv_bfloat162 v0, v1, w0, w1;
            v0.x = __float2bfloat16(cr[ma][nb][0]); v0.y = __float2bfloat16(cr[ma][nb][1]);
            v1.x = __float2bfloat16(cr[ma][nb][2]); v1.y = __float2bfloat16(cr[ma][nb][3]);
            w0.x = __float2bfloat16(ci[ma][nb][0]); w0.y = __float2bfloat16(ci[ma][nb][1]);
            w1.x = __float2bfloat16(ci[ma][nb][2]); w1.y = __float2bfloat16(ci[ma][nb][3]);
            *(__nv_bfloat162*)&d.Cr[(size_t)r0*d.ldc + c0]     = v0;
            *(__nv_bfloat162*)&d.Cr[(size_t)(r0+8)*d.ldc + c0] = v1;
            *(__nv_bfloat162*)&d.Ci[(size_t)r0*d.ldc + c0]     = w0;
            *(__nv_bfloat162*)&d.Ci[(size_t)(r0+8)*d.ldc + c0] = w1;
        }
}

// ------------ X = Ux * gathered(W), bf16 out ------------
__global__ void __launch_bounds__(256, 2)
gemm_gatherX()
{
    int m0 = blockIdx.y * 64, n0 = blockIdx.x * 64;
    float cr[2][2][4] = {}, ci[2][2][4] = {};
    mainloop_bf(true, g_Uxh_r, g_Uxh_i, 256, g_Wh_r, g_Wh_i, 8192, m0, n0, cr, ci);

    int tid = threadIdx.x, warp = tid >> 5, lane = tid & 31;
    int g = lane >> 2, t = lane & 3;
    int wm = (warp & 1) << 5, wn = (warp >> 1) << 4;
#pragma unroll
    for (int ma = 0; ma < 2; ma++)
#pragma unroll
        for (int nb = 0; nb < 2; nb++) {
            int r0 = m0 + wm + ma*16 + g;
            int c0 = n0 + wn + nb*8 + 2*t;
            __nv_bfloat162 v0, v1, w0, w1;
            v0.x = __float2bfloat16(cr[ma][nb][0]); v0.y = __float2bfloat16(cr[ma][nb][1]);
            v1.x = __float2bfloat16(cr[ma][nb][2]); v1.y = __float2bfloat16(cr[ma][nb][3]);
            w0.x = __float2bfloat16(ci[ma][nb][0]); w0.y = __float2bfloat16(ci[ma][nb][1]);
            w1.x = __float2bfloat16(ci[ma][nb][2]); w1.y = __float2bfloat16(ci[ma][nb][3]);
            *(__nv_bfloat162*)&g_Xh_r[(size_t)r0*NX + c0]     = v0;
            *(__nv_bfloat162*)&g_Xh_r[(size_t)(r0+8)*NX + c0] = v1;
            *(__nv_bfloat162*)&g_Xh_i[(size_t)r0*NX + c0]     = w0;
            *(__nv_bfloat162*)&g_Xh_i[(size_t)(r0+8)*NX + c0] = w1;
        }
}

// ------------ staircase measurement (flat grid, bf16 mma, fp32 epilogue) ------------
__global__ void __launch_bounds__(256, 2)
measure_mma()
{
    int bx = blockIdx.x;
    int ap = 0;
    while (c_off[ap + 1] <= bx) ap++;
    int n0 = (bx - c_off[ap]) * 64;
    int m0 = blockIdx.y * 64;
    int Neff = 4 * (32 - ap) * (33 - ap);

    float cr[2][2][4] = {}, ci[2][2][4] = {};
    mainloop_bf(false,
                g_Gh_r + (size_t)ap*65536, g_Gh_i + (size_t)ap*65536, 256,
                g_Xh_r, g_Xh_i, NX, m0, n0, cr, ci);

    int tid = threadIdx.x, warp = tid >> 5, lane = tid & 31;
    int g = lane >> 2, t = lane & 3;
    int wm = (warp & 1) << 5, wn = (warp >> 1) << 4;
    float lb2 = g_lb2;
#pragma unroll
    for (int ma = 0; ma < 2; ma++)
#pragma unroll
        for (int nb = 0; nb < 2; nb++) {
            int r0 = m0 + wm + ma*16 + g;
            int c0 = n0 + wn + nb*8 + 2*t;
#pragma unroll
            for (int jj = 0; jj < 2; jj++) {
                int c = c0 + jj;
                if (c < Neff) {
                    float coef = lb2 * g_gpow[ap + g_map_a[c]];
                    int tb = ap * 8 + g_map_tb[c];
                    float q0 = cr[ma][nb][jj]*cr[ma][nb][jj] + ci[ma][nb][jj]*ci[ma][nb][jj];
                    float q1 = cr[ma][nb][jj+2]*cr[ma][nb][jj+2] + ci[ma][nb][jj+2]*ci[ma][nb][jj+2];
                    atomicAdd(&g_probs[tb*256 + r0],     coef * q0);
                    atomicAdd(&g_probs[tb*256 + r0 + 8], coef * q1);
                }
            }
        }
}

// ------------ MLP head + log_softmax (k-parallel) ------------
__global__ void head(const float* __restrict__ W1, const float* __restrict__ b1,
                     const float* __restrict__ W2, const float* __restrict__ b2,
                     float* __restrict__ out)
{
    int blk = blockIdx.x;        // t*8+b
    int t = blk >> 3, b = blk & 7;
    int tid = threadIdx.x;       // 256
    int j = tid & 63, q = tid >> 6;
    __shared__ float part[4][64];
    __shared__ float h1[64];
    __shared__ float o[6];
    __shared__ float red[2];
    const float* p = g_probs + blk * 256;
    float acc = 0.f;
    int k0 = q * 64;
    for (int k = k0; k < k0 + 64; k++) acc = fmaf(p[k], W1[k*64 + j], acc);
    part[q][j] = acc;
    __syncthreads();
    if (tid < 64) {
        float s = part[0][tid] + part[1][tid] + part[2][tid] + part[3][tid] + b1[tid];
        h1[tid] = fmaxf(s, 0.f);
    }
    __syncthreads();
    if (tid < 6) {
        float a2 = b2[tid];
        for (int qq = 0; qq < 64; qq++) a2 = fmaf(h1[qq], W2[qq*6 + tid], a2);
        o[tid] = tanhf(a2);
    }
    __syncthreads();
    if (tid == 0) {
        float mx = o[0];
        for (int c = 1; c < 6; c++) mx = fmaxf(mx, o[c]);
        float se = 0.f;
        for (int c = 0; c < 6; c++) se += expf(o[c] - mx);
        red[0] = mx; red[1] = logf(se);
    }
    __syncthreads();
    if (tid < 6) out[(b*32 + t)*6 + tid] = o[tid] - red[0] - red[1];
}

// ------------ host helpers ------------
static GemmDesc mk(const bf16* Ar, const bf16* Ai, const bf16* Br, const bf16* Bi,
                   bf16* Cr, bf16* Ci, int lda, int ldb, int ldc, int ntx)
{
    GemmDesc d;
    d.Ar = Ar; d.Ai = Ai; d.Br = Br; d.Bi = Bi; d.Cr = Cr; d.Ci = Ci;
    d.lda = lda; d.ldb = ldb; d.ldc = ldc; d.ntx = ntx;
    return d;
}

// ------------ launch ------------
extern "C" void kernel_launch(void* const* d_in, const int* in_sizes, int n_in,
                              void* d_out, int out_size)
{
    const float* xt    = (const float*)d_in[0];
    const float* xa    = (const float*)d_in[1];
    const float* xv    = (const float*)d_in[2];
    const float* smask = (const float*)d_in[3];
    const float* Wt    = (const float*)d_in[4];
    const float* bt    = (const float*)d_in[5];
    const float* Wa    = (const float*)d_in[6];
    const float* ba    = (const float*)d_in[7];
    const float* Wv    = (const float*)d_in[8];
    const float* bv    = (const float*)d_in[9];
    const float* Pt    = (const float*)d_in[10];
    const float* Pa    = (const float*)d_in[11];
    const float* Pv    = (const float*)d_in[12];
    const float* Uxr   = (const float*)d_in[13];
    const float* Uxi   = (const float*)d_in[14];
    const float* Uhr   = (const float*)d_in[15];
    const float* Uhi   = (const float*)d_in[16];
    const float* Lam   = (const float*)d_in[17];
    const float* Kr    = (const float*)d_in[18];
    const float* Ki    = (const float*)d_in[19];
    const float* W1    = (const float*)d_in[20];
    const float* b1    = (const float*)d_in[21];
    const float* W2    = (const float*)d_in[22];
    const float* b2    = (const float*)d_in[23];
    float* out = (float*)d_out;

    bf16 *Wr, *Wi, *Pr, *Pi, *Gr, *Gi, *psir, *psii, *Uxhr, *Uxhi, *Uhhr, *Uhhi;
    cudaGetSymbolAddress((void**)&Wr,   g_Wh_r);
    cudaGetSymbolAddress((void**)&Wi,   g_Wh_i);
    cudaGetSymbolAddress((void**)&Pr,   g_Ph_r);
    cudaGetSymbolAddress((void**)&Pi,   g_Ph_i);
    cudaGetSymbolAddress((void**)&Gr,   g_Gh_r);
    cudaGetSymbolAddress((void**)&Gi,   g_Gh_i);
    cudaGetSymbolAddress((void**)&psir, g_psih_r);
    cudaGetSymbolAddress((void**)&psii, g_psih_i);
    cudaGetSymbolAddress((void**)&Uxhr, g_Uxh_r);
    cudaGetSymbolAddress((void**)&Uxhi, g_Uxh_i);
    cudaGetSymbolAddress((void**)&Uhhr, g_Uhh_r);
    cudaGetSymbolAddress((void**)&Uhhi, g_Uhh_i);

    cudaFuncSetAttribute(gemm_multi,  cudaFuncAttributeMaxDynamicSharedMemorySize, SMEM_BYTES);
    cudaFuncSetAttribute(gemm_gatherX, cudaFuncAttributeMaxDynamicSharedMemorySize, SMEM_BYTES);
    cudaFuncSetAttribute(measure_mma, cudaFuncAttributeMaxDynamicSharedMemorySize, SMEM_BYTES);

    prep_all<<<785, 256>>>(Lam, xt, xa, xv, smask, Wt, bt, Wa, ba, Wv, bv,
                           Pt, Pa, Pv, Kr, Ki, Uxr, Uxi, Uhr, Uhi);

    // L1: Phi = Ux*Psi -> W[0] | G1 = G0*Uh | P2 = Uh*Uh
    {
        GemmDesc d0 = mk(Uxhr, Uxhi, psir, psii, Wr, Wi, 256, 256, 8192, 4);
        GemmDesc d1 = mk(Gr, Gi, Uhhr, Uhhi, Gr + 65536, Gi + 65536, 256, 256, 256, 4);
        GemmDesc d2 = mk(Uhhr, Uhhi, Uhhr, Uhhi, Pr, Pi, 256, 256, 256, 4);
        gemm_multi<<<48, 256, SMEM_BYTES>>>(d0, d1, d2, 16, 16);
    }
    // L2: W1 = Uh*W0 | G[2:4] = G[0:2]*P2 | P4 = P2*P2
    {
        GemmDesc d0 = mk(Uhhr, Uhhi, Wr, Wi, Wr + 256, Wi + 256, 256, 8192, 8192, 4);
        GemmDesc d1 = mk(Gr, Gi, Pr, Pi, Gr + 2*65536, Gi + 2*65536, 256, 256, 256, 4);
        GemmDesc d2 = mk(Pr, Pi, Pr, Pi, Pr + 65536, Pi + 65536, 256, 256, 256, 4);
        gemm_multi<<<64, 256, SMEM_BYTES>>>(d0, d1, d2, 16, 32);
    }
    // L3: W[2:4] = P2*W[0:2] | G[4:8] = G[0:4]*P4 | P8 = P4*P4
    {
        GemmDesc d0 = mk(Pr, Pi, Wr, Wi, Wr + 512, Wi + 512, 256, 8192, 8192, 8);
        GemmDesc d1 = mk(Gr, Gi, Pr + 65536, Pi + 65536, Gr + 4*65536, Gi + 4*65536, 256, 256, 256, 4);
        GemmDesc d2 = mk(Pr + 65536, Pi + 65536, Pr + 65536, Pi + 65536, Pr + 131072, Pi + 131072, 256, 256, 256, 4);
        gemm_multi<<<112, 256, SMEM_BYTES>>>(d0, d1, d2, 32, 64);
    }
    // L4: W[4:8] = P4*W[0:4] | G[8:16] = G[0:8]*P8 | P16 = P8*P8
    {
        GemmDesc d0 = mk(Pr + 65536, Pi + 65536, Wr, Wi, Wr + 1024, Wi + 1024, 256, 8192, 8192, 16);
        GemmDesc d1 = mk(Gr, Gi, Pr + 131072, Pi + 131072, Gr + 8*65536, Gi + 8*65536, 256, 256, 256, 4);
        GemmDesc d2 = mk(Pr + 131072, Pi + 131072, Pr + 131072, Pi + 131072, Pr + 196608, Pi + 196608, 256, 256, 256, 4);
        gemm_multi<<<208, 256, SMEM_BYTES>>>(d0, d1, d2, 64, 128);
    }
    // L5: W[8:16] = P8*W[0:8] | G[16:32] = G[0:16]*P16
    {
        GemmDesc d0 = mk(Pr + 131072, Pi + 131072, Wr, Wi, Wr + 2048, Wi + 2048, 256, 8192, 8192, 32);
        GemmDesc d1 = mk(Gr, Gi, Pr + 196608, Pi + 196608, Gr + 16*65536, Gi + 16*65536, 256, 256, 256, 4);
        gemm_multi<<<384, 256, SMEM_BYTES>>>(d0, d1, d0, 128, 256);
    }
    // L6: W[16:32] = P16*W[0:16]
    {
        GemmDesc d0 = mk(Pr + 196608, Pi + 196608, Wr, Wi, Wr + 4096, Wi + 4096, 256, 8192, 8192, 64);
        gemm_multi<<<256, 256, SMEM_BYTES>>>(d0, d0, d0, 256, 0);
    }
    // X = Ux * gathered(W)
    gemm_gatherX<<<dim3(66, 4), 256, SMEM_BYTES>>>();

    measure_mma<<<dim3(762, 4), 256, SMEM_BYTES>>>();
    head<<<256, 256>>>(W1, b1, W2, b2, out);
}